// round 3
// baseline (speedup 1.0000x reference)
#include <cuda_runtime.h>
#include <math.h>
#include <stdint.h>

#define BATCH 8
#define CIN   64
#define MID   32
#define HH    256
#define WW    256
#define NSEL  64
#define BN_EPS 1e-5f
#define HWSZ  (HH*WW)

// ---------------- device globals (scratch + folded params) ----------------
__device__ float g_t1[(size_t)BATCH*MID*HWSZ];     // t1 = bn(conv1x1(x, w_3x3_1))

__device__ float g_wm[MID*CIN*9];   // main 3x3, BN-folded
__device__ float g_bm[MID];
__device__ float g_w1[MID*CIN];     // 1x1, BN-folded
__device__ float g_b1[MID];
__device__ float g_wp1[MID*CIN];    // 3x3_1 (t1 producer), BN-folded
__device__ float g_bp1[MID];
__device__ float g_wp2[MID*MID*9];  // 3x3_2, BN-folded
__device__ float g_bp2[MID];
__device__ float g_wa[MID*CIN];     // avg-branch 1x1, both BNs and /9 folded
__device__ float g_ba1[MID];        // per-pixel bias (inside image), *inv2/9
__device__ float g_ba2[MID];        // final additive bias

// selection lists: branch b in {0:main,1:1x1,2:3x3,3:avg}
__device__ int   g_cnt[4];
__device__ int   g_lch[4][MID];
__device__ int   g_lpos[4][MID];
__device__ float g_lscale[4][MID];

// ---------------- setup: top-k + BN folding ----------------
__device__ __forceinline__ void bnfold(const float* bn, int c, float& inv, float& bias) {
    float g = bn[c], b = bn[MID + c], m = bn[2*MID + c], v = bn[3*MID + c];
    inv  = g * rsqrtf(v + BN_EPS);
    bias = b - m * inv;
}

__global__ void k_setup(const float* __restrict__ w_main, const float* __restrict__ bn_main,
                        const float* __restrict__ w_1x1,  const float* __restrict__ bn_1x1,
                        const float* __restrict__ w31,    const float* __restrict__ bn31,
                        const float* __restrict__ w32,    const float* __restrict__ bn32,
                        const float* __restrict__ w_avg,  const float* __restrict__ bnA1,
                        const float* __restrict__ bnA2,   const float* __restrict__ c_score)
{
    __shared__ float sc[128];
    const int tid = threadIdx.x;
    if (tid < 4) g_cnt[tid] = 0;
    if (tid < 128) sc[tid] = c_score[tid];
    __syncthreads();

    if (tid < 128) {
        float v = sc[tid];
        int rank = 0;
        for (int k = 0; k < 128; k++) {
            float u = sc[k];
            if (u > v || (u == v && k < tid)) rank++;
        }
        if (rank < NSEL) {   // selected; output channel == rank (descending stable sort)
            int br   = tid >> 5;
            int slot = atomicAdd(&g_cnt[br], 1);
            g_lch[br][slot]    = tid & 31;
            g_lpos[br][slot]   = rank;
            g_lscale[br][slot] = 1.f / (1.f + expf(-v));
        }
    }

    // fold BN into weights (inv recomputed per element: trivial total work)
    for (int i = tid; i < MID*CIN*9; i += blockDim.x) {
        int oc = i / (CIN*9); float inv, bi; bnfold(bn_main, oc, inv, bi);
        g_wm[i] = w_main[i] * inv;
    }
    for (int i = tid; i < MID*CIN; i += blockDim.x) {
        int oc = i / CIN; float inv, bi;
        bnfold(bn_1x1, oc, inv, bi);  g_w1[i]  = w_1x1[i] * inv;
        bnfold(bn31,  oc, inv, bi);   g_wp1[i] = w31[i]  * inv;
        float i1, c1, i2, c2;
        bnfold(bnA1, oc, i1, c1); bnfold(bnA2, oc, i2, c2);
        g_wa[i] = w_avg[i] * i1 * i2 * (1.f/9.f);
    }
    for (int i = tid; i < MID*MID*9; i += blockDim.x) {
        int oc = i / (MID*9); float inv, bi; bnfold(bn32, oc, inv, bi);
        g_wp2[i] = w32[i] * inv;
    }
    if (tid < MID) {
        float inv, bi;
        bnfold(bn_main, tid, inv, bi); g_bm[tid]  = bi;
        bnfold(bn_1x1,  tid, inv, bi); g_b1[tid]  = bi;
        bnfold(bn31,    tid, inv, bi); g_bp1[tid] = bi;
        bnfold(bn32,    tid, inv, bi); g_bp2[tid] = bi;
        float i1, c1, i2, c2;
        bnfold(bnA1, tid, i1, c1); bnfold(bnA2, tid, i2, c2);
        g_ba1[tid] = c1 * i2 * (1.f/9.f);
        g_ba2[tid] = c2;
    }
}

// ---------------- t1 producer: 1x1 conv 64->32, register blocked ----------------
// One block: 2 rows x 256 cols (512 px). 256 threads, 2 px each.
#define SMEM_T1 ((CIN*512 + MID*CIN + MID) * 4)
__global__ __launch_bounds__(256, 1) void k_t1(const float* __restrict__ x)
{
    extern __shared__ float sm[];
    float* xsr = sm;               // [64][512]
    float* ws  = sm + CIN*512;     // [32][64]
    float* bs  = ws + MID*CIN;     // [32]
    const int tid = threadIdx.x;
    const int blk = blockIdx.x;             // 0 .. B*H/2-1
    const int b   = blk / (HH/2);
    const int r0  = (blk % (HH/2)) * 2;

    const float* xb = x + (size_t)b*CIN*HWSZ + (size_t)r0*WW;
    for (int i = tid; i < CIN*512; i += 256) {
        int ch = i >> 9, p = i & 511;
        xsr[i] = xb[(size_t)ch*HWSZ + (p >> 8)*WW + (p & 255)];
    }
    for (int i = tid; i < MID*CIN; i += 256) ws[i] = g_wp1[i];
    if (tid < MID) bs[tid] = g_bp1[tid];
    __syncthreads();

    float* outb = g_t1 + (size_t)b*MID*HWSZ + (size_t)r0*WW + tid;
    #pragma unroll
    for (int ob = 0; ob < 4; ob++) {
        float a0[8], a1[8];
        #pragma unroll
        for (int o = 0; o < 8; o++) { float bb = bs[ob*8+o]; a0[o] = bb; a1[o] = bb; }
        #pragma unroll
        for (int icb = 0; icb < 8; icb++) {
            float xv0[8], xv1[8];
            #pragma unroll
            for (int j = 0; j < 8; j++) {
                xv0[j] = xsr[(icb*8+j)*512 + tid];
                xv1[j] = xsr[(icb*8+j)*512 + 256 + tid];
            }
            #pragma unroll
            for (int o = 0; o < 8; o++) {
                const float* wr = ws + (ob*8+o)*CIN + icb*8;
                #pragma unroll
                for (int j = 0; j < 8; j++) {
                    float w = wr[j];
                    a0[o] += xv0[j]*w; a1[o] += xv1[j]*w;
                }
            }
        }
        #pragma unroll
        for (int o = 0; o < 8; o++) {
            int oc = ob*8+o;
            outb[(size_t)oc*HWSZ]      = a0[o];
            outb[(size_t)oc*HWSZ + WW] = a1[o];
        }
    }
}

// ---------------- fused main/1x1/avg kernel ----------------
// Tile: 16 rows x 32 cols. 256 threads, each 2 vertically-adjacent px.
// smem: xs[64][18][34] (haloed) + wbuf[576] + t2s[18][34]
#define SMEM_A ((CIN*612 + 576 + 612) * 4)
__global__ __launch_bounds__(256, 1) void k_main(const float* __restrict__ x,
                                                 float* __restrict__ out)
{
    extern __shared__ float sm[];
    float* xs   = sm;               // 64*612
    float* wbuf = sm + CIN*612;     // 576
    float* t2s  = wbuf + 576;       // 612
    const int tid = threadIdx.x;
    const int tx  = tid & 31;
    const int ty  = tid >> 5;       // 0..7
    const int r0  = ty * 2;         // local rows r0, r0+1
    const int b   = blockIdx.z;
    const int ty0 = blockIdx.y * 16;
    const int tx0 = blockIdx.x * 32;

    const float* xb = x + (size_t)b*CIN*HWSZ;
    for (int i = tid; i < CIN*612; i += 256) {
        int ch = i / 612, rem = i % 612;
        int rr = rem / 34, cc = rem % 34;
        int gy = ty0 + rr - 1, gx = tx0 + cc - 1;
        float v = 0.f;
        if ((unsigned)gy < HH && (unsigned)gx < WW)
            v = xb[(size_t)ch*HWSZ + gy*WW + gx];
        xs[i] = v;
    }
    __syncthreads();

    float* ob = out + (size_t)b*NSEL*HWSZ;
    const int gy = ty0 + r0, gx = tx0 + tx;

    // ---- main branch: 3x3 over x ----
    const int nm = g_cnt[0];
    for (int k = 0; k < nm; k++) {
        int oc = g_lch[0][k], pos = g_lpos[0][k]; float scl = g_lscale[0][k];
        for (int i = tid; i < CIN*9; i += 256) wbuf[i] = g_wm[oc*CIN*9 + i];
        __syncthreads();
        float bias = g_bm[oc];
        float a0 = 0.f, a1 = 0.f;
        #pragma unroll 4
        for (int ic = 0; ic < CIN; ic++) {
            const float* p = xs + ic*612 + r0*34 + tx;
            float v00=p[0],  v01=p[1],  v02=p[2];
            float v10=p[34], v11=p[35], v12=p[36];
            float v20=p[68], v21=p[69], v22=p[70];
            float v30=p[102],v31=p[103],v32=p[104];
            const float* wp = wbuf + ic*9;
            float w0=wp[0],w1=wp[1],w2=wp[2],w3=wp[3],w4=wp[4],w5=wp[5],w6=wp[6],w7=wp[7],w8=wp[8];
            a0 += v00*w0+v01*w1+v02*w2 + v10*w3+v11*w4+v12*w5 + v20*w6+v21*w7+v22*w8;
            a1 += v10*w0+v11*w1+v12*w2 + v20*w3+v21*w4+v22*w5 + v30*w6+v31*w7+v32*w8;
        }
        float* o = ob + (size_t)pos*HWSZ + gy*WW + gx;
        o[0]  = (a0 + bias) * scl;
        o[WW] = (a1 + bias) * scl;
        __syncthreads();
    }

    // ---- 1x1 branch ----
    const int n1 = g_cnt[1];
    for (int k = 0; k < n1; k++) {
        int oc = g_lch[1][k], pos = g_lpos[1][k]; float scl = g_lscale[1][k];
        for (int i = tid; i < CIN; i += 256) wbuf[i] = g_w1[oc*CIN + i];
        __syncthreads();
        float bias = g_b1[oc];
        float a0 = 0.f, a1 = 0.f;
        const float* p0 = xs + (r0+1)*34 + (tx+1);
        #pragma unroll 8
        for (int ic = 0; ic < CIN; ic++) {
            float w = wbuf[ic];
            a0 += p0[ic*612]      * w;
            a1 += p0[ic*612 + 34] * w;
        }
        float* o = ob + (size_t)pos*HWSZ + gy*WW + gx;
        o[0]  = (a0 + bias) * scl;
        o[WW] = (a1 + bias) * scl;
        __syncthreads();
    }

    // ---- avg branch: 1x1 (fully folded) -> 3x3 sum -> +bias ----
    const int na = g_cnt[3];
    for (int k = 0; k < na; k++) {
        int oc = g_lch[3][k], pos = g_lpos[3][k]; float scl = g_lscale[3][k];
        for (int i = tid; i < CIN; i += 256) wbuf[i] = g_wa[oc*CIN + i];
        __syncthreads();
        float ba1 = g_ba1[oc], ba2 = g_ba2[oc];
        for (int i = tid; i < 612; i += 256) {
            int rr = i / 34, cc = i % 34;
            int yy = ty0 + rr - 1, xx = tx0 + cc - 1;
            float v = 0.f;
            if ((unsigned)yy < HH && (unsigned)xx < WW) {
                float s = ba1;
                const float* p = xs + i;
                #pragma unroll 8
                for (int ic = 0; ic < CIN; ic++) s += p[ic*612] * wbuf[ic];
                v = s;
            }
            t2s[i] = v;
        }
        __syncthreads();
        const float* q = t2s + r0*34 + tx;
        float s0 = q[0]+q[1]+q[2] + q[34]+q[35]+q[36] + q[68]+q[69]+q[70];
        float s1 = q[34]+q[35]+q[36] + q[68]+q[69]+q[70] + q[102]+q[103]+q[104];
        float* o = ob + (size_t)pos*HWSZ + gy*WW + gx;
        o[0]  = (s0 + ba2) * scl;
        o[WW] = (s1 + ba2) * scl;
        __syncthreads();
    }
}

// ---------------- 3x3 branch: conv3x3 over t1 (32 ch) ----------------
#define SMEM_B ((MID*612 + 288) * 4)
__global__ __launch_bounds__(256, 1) void k_b3(float* __restrict__ out)
{
    extern __shared__ float sm[];
    float* t1s  = sm;               // 32*612
    float* wbuf = sm + MID*612;     // 288
    const int tid = threadIdx.x;
    const int tx  = tid & 31;
    const int ty  = tid >> 5;
    const int r0  = ty * 2;
    const int b   = blockIdx.z;
    const int ty0 = blockIdx.y * 16;
    const int tx0 = blockIdx.x * 32;

    const float* tb = g_t1 + (size_t)b*MID*HWSZ;
    for (int i = tid; i < MID*612; i += 256) {
        int ch = i / 612, rem = i % 612;
        int rr = rem / 34, cc = rem % 34;
        int gy = ty0 + rr - 1, gx = tx0 + cc - 1;
        float v = 0.f;
        if ((unsigned)gy < HH && (unsigned)gx < WW)
            v = tb[(size_t)ch*HWSZ + gy*WW + gx];
        t1s[i] = v;
    }
    __syncthreads();

    float* ob = out + (size_t)b*NSEL*HWSZ;
    const int gy = ty0 + r0, gx = tx0 + tx;
    const int n3 = g_cnt[2];
    for (int k = 0; k < n3; k++) {
        int oc = g_lch[2][k], pos = g_lpos[2][k]; float scl = g_lscale[2][k];
        for (int i = tid; i < MID*9; i += 256) wbuf[i] = g_wp2[oc*MID*9 + i];
        __syncthreads();
        float bias = g_bp2[oc];
        float a0 = 0.f, a1 = 0.f;
        #pragma unroll 4
        for (int ic = 0; ic < MID; ic++) {
            const float* p = t1s + ic*612 + r0*34 + tx;
            float v00=p[0],  v01=p[1],  v02=p[2];
            float v10=p[34], v11=p[35], v12=p[36];
            float v20=p[68], v21=p[69], v22=p[70];
            float v30=p[102],v31=p[103],v32=p[104];
            const float* wp = wbuf + ic*9;
            float w0=wp[0],w1=wp[1],w2=wp[2],w3=wp[3],w4=wp[4],w5=wp[5],w6=wp[6],w7=wp[7],w8=wp[8];
            a0 += v00*w0+v01*w1+v02*w2 + v10*w3+v11*w4+v12*w5 + v20*w6+v21*w7+v22*w8;
            a1 += v10*w0+v11*w1+v12*w2 + v20*w3+v21*w4+v22*w5 + v30*w6+v31*w7+v32*w8;
        }
        float* o = ob + (size_t)pos*HWSZ + gy*WW + gx;
        o[0]  = (a0 + bias) * scl;
        o[WW] = (a1 + bias) * scl;
        __syncthreads();
    }
}

// ---------------- launch ----------------
extern "C" void kernel_launch(void* const* d_in, const int* in_sizes, int n_in,
                              void* d_out, int out_size)
{
    const float* x       = (const float*)d_in[0];
    const float* w_main  = (const float*)d_in[1];
    const float* bn_main = (const float*)d_in[2];
    const float* w_1x1   = (const float*)d_in[3];
    const float* bn_1x1  = (const float*)d_in[4];
    const float* w31     = (const float*)d_in[5];
    const float* bn31    = (const float*)d_in[6];
    const float* w32     = (const float*)d_in[7];
    const float* bn32    = (const float*)d_in[8];
    const float* w_avg   = (const float*)d_in[9];
    const float* bnA1    = (const float*)d_in[10];
    const float* bnA2    = (const float*)d_in[11];
    const float* c_score = (const float*)d_in[12];
    float* out = (float*)d_out;

    cudaFuncSetAttribute(k_t1,   cudaFuncAttributeMaxDynamicSharedMemorySize, SMEM_T1);
    cudaFuncSetAttribute(k_main, cudaFuncAttributeMaxDynamicSharedMemorySize, SMEM_A);
    cudaFuncSetAttribute(k_b3,   cudaFuncAttributeMaxDynamicSharedMemorySize, SMEM_B);

    k_setup<<<1, 256>>>(w_main, bn_main, w_1x1, bn_1x1, w31, bn31, w32, bn32,
                        w_avg, bnA1, bnA2, c_score);
    k_t1<<<BATCH*HH/2, 256, SMEM_T1>>>(x);
    dim3 grid(WW/32, HH/16, BATCH);
    k_main<<<grid, 256, SMEM_A>>>(x, out);
    k_b3<<<grid, 256, SMEM_B>>>(out);
}

// round 6
// speedup vs baseline: 1.3028x; 1.3028x over previous
#include <cuda_runtime.h>
#include <math.h>
#include <stdint.h>

#define BATCH 8
#define CIN   64
#define MID   32
#define HH    256
#define WW    256
#define NSEL  64
#define BN_EPS 1e-5f
#define HWSZ  (HH*WW)

// ---------------- device globals (scratch + folded params) ----------------
__device__ float g_t1[(size_t)BATCH*MID*HWSZ];     // t1 = bn(conv1x1(x, w_3x3_1))

__device__ float g_wm[MID*CIN*9];   // main 3x3, BN-folded
__device__ float g_bm[MID];
__device__ float g_w1[MID*CIN];     // 1x1, BN-folded
__device__ float g_b1[MID];
__device__ float g_wp1[MID*CIN];    // 3x3_1 (t1 producer), BN-folded
__device__ float g_bp1[MID];
__device__ float g_wp2[MID*MID*9];  // 3x3_2, BN-folded
__device__ float g_bp2[MID];
__device__ float g_wa[MID*CIN];     // avg-branch 1x1, both BNs and /9 folded
__device__ float g_ba1[MID];        // per-pixel bias (inside image)
__device__ float g_ba2[MID];        // final additive bias

// selection lists: branch b in {0:main,1:1x1,2:3x3,3:avg}; counts padded to x4
__device__ int   g_cnt[4];
__device__ int   g_lch[4][MID];
__device__ int   g_lpos[4][MID];
__device__ float g_lscale[4][MID];

// ---------------- setup: top-k + BN folding ----------------
__device__ __forceinline__ void bnfold(const float* bn, int c, float& inv, float& bias) {
    float g = bn[c], b = bn[MID + c], m = bn[2*MID + c], v = bn[3*MID + c];
    inv  = g * rsqrtf(v + BN_EPS);
    bias = b - m * inv;
}

__global__ void k_setup(const float* __restrict__ w_main, const float* __restrict__ bn_main,
                        const float* __restrict__ w_1x1,  const float* __restrict__ bn_1x1,
                        const float* __restrict__ w31,    const float* __restrict__ bn31,
                        const float* __restrict__ w32,    const float* __restrict__ bn32,
                        const float* __restrict__ w_avg,  const float* __restrict__ bnA1,
                        const float* __restrict__ bnA2,   const float* __restrict__ c_score)
{
    __shared__ float sc[128];
    const int tid = threadIdx.x;
    if (tid < 4) g_cnt[tid] = 0;
    if (tid < 128) sc[tid] = c_score[tid];
    __syncthreads();

    if (tid < 128) {
        float v = sc[tid];
        int rank = 0;
        for (int k = 0; k < 128; k++) {
            float u = sc[k];
            if (u > v || (u == v && k < tid)) rank++;
        }
        if (rank < NSEL) {   // selected; output channel == rank (descending stable sort)
            int br   = tid >> 5;
            int slot = atomicAdd(&g_cnt[br], 1);
            g_lch[br][slot]    = tid & 31;
            g_lpos[br][slot]   = rank;
            g_lscale[br][slot] = 1.f / (1.f + expf(-v));
        }
    }
    __syncthreads();
    // pad lists to a multiple of 4 (duplicates of slot 0 -> identical redundant stores)
    if (tid < 4) {
        int n  = g_cnt[tid];
        int np = (n + 3) & ~3;
        for (int s = n; s < np; s++) {
            g_lch[tid][s]    = g_lch[tid][0];
            g_lpos[tid][s]   = g_lpos[tid][0];
            g_lscale[tid][s] = g_lscale[tid][0];
        }
        g_cnt[tid] = np;
    }

    // fold BN into weights
    for (int i = tid; i < MID*CIN*9; i += blockDim.x) {
        int oc = i / (CIN*9); float inv, bi; bnfold(bn_main, oc, inv, bi);
        g_wm[i] = w_main[i] * inv;
    }
    for (int i = tid; i < MID*CIN; i += blockDim.x) {
        int oc = i / CIN; float inv, bi;
        bnfold(bn_1x1, oc, inv, bi);  g_w1[i]  = w_1x1[i] * inv;
        bnfold(bn31,  oc, inv, bi);   g_wp1[i] = w31[i]  * inv;
        float i1, c1, i2, c2;
        bnfold(bnA1, oc, i1, c1); bnfold(bnA2, oc, i2, c2);
        g_wa[i] = w_avg[i] * i1 * i2 * (1.f/9.f);
    }
    for (int i = tid; i < MID*MID*9; i += blockDim.x) {
        int oc = i / (MID*9); float inv, bi; bnfold(bn32, oc, inv, bi);
        g_wp2[i] = w32[i] * inv;
    }
    if (tid < MID) {
        float inv, bi;
        bnfold(bn_main, tid, inv, bi); g_bm[tid]  = bi;
        bnfold(bn_1x1,  tid, inv, bi); g_b1[tid]  = bi;
        bnfold(bn31,    tid, inv, bi); g_bp1[tid] = bi;
        bnfold(bn32,    tid, inv, bi); g_bp2[tid] = bi;
        float i1, c1, i2, c2;
        bnfold(bnA1, tid, i1, c1); bnfold(bnA2, tid, i2, c2);
        g_ba1[tid] = c1 * i2 * (1.f/9.f);
        g_ba2[tid] = c2;
    }
}

// ---------------- t1 producer: 1x1 conv 64->32 ----------------
// One block: 2 rows x 256 cols (512 px). 256 threads, 2 px each, all 32 oc in regs.
// x transposed to [px][ch] with stride 68 -> conflict-free float4 LDS.
#define XSTR 68
#define SMEM_T1 ((512*XSTR + MID*CIN + MID) * 4)
__global__ __launch_bounds__(256, 1) void k_t1(const float* __restrict__ x)
{
    extern __shared__ float sm[];
    float* xsr = sm;                 // [512][68]
    float* ws  = sm + 512*XSTR;      // [32][64]
    float* bs  = ws + MID*CIN;       // [32]
    const int tid = threadIdx.x;
    const int blk = blockIdx.x;
    const int b   = blk / (HH/2);
    const int r0  = (blk % (HH/2)) * 2;

    const float* xb = x + (size_t)b*CIN*HWSZ + (size_t)r0*WW;
    for (int i = tid; i < CIN*512; i += 256) {
        int ch = i >> 9, p = i & 511;
        xsr[p*XSTR + ch] = xb[(size_t)ch*HWSZ + (p >> 8)*WW + (p & 255)];
    }
    for (int i = tid; i < MID*CIN; i += 256) ws[i] = g_wp1[i];
    if (tid < MID) bs[tid] = g_bp1[tid];
    __syncthreads();

    float a0[MID], a1[MID];
    #pragma unroll
    for (int o = 0; o < MID; o++) { float bb = bs[o]; a0[o] = bb; a1[o] = bb; }

    const float* xp0 = xsr + tid*XSTR;
    const float* xp1 = xsr + (tid+256)*XSTR;
    #pragma unroll 2
    for (int ic = 0; ic < CIN; ic += 4) {
        float4 xv0 = *(const float4*)(xp0 + ic);
        float4 xv1 = *(const float4*)(xp1 + ic);
        #pragma unroll
        for (int o = 0; o < MID; o++) {
            float4 w = *(const float4*)(ws + o*CIN + ic);
            a0[o] += xv0.x*w.x + xv0.y*w.y + xv0.z*w.z + xv0.w*w.w;
            a1[o] += xv1.x*w.x + xv1.y*w.y + xv1.z*w.z + xv1.w*w.w;
        }
    }

    float* outb = g_t1 + (size_t)b*MID*HWSZ + (size_t)r0*WW + tid;
    #pragma unroll
    for (int o = 0; o < MID; o++) {
        outb[(size_t)o*HWSZ]      = a0[o];
        outb[(size_t)o*HWSZ + WW] = a1[o];
    }
}

// ---------------- fused main/1x1/avg kernel ----------------
// Tile 16x32, 256 threads, 2 vertical px/thread, 4 output channels/iteration.
// smem: xs[64][18*34] + wbuf[4*64*12] + t2s[4][612]
#define SMEM_A ((CIN*612 + 4*CIN*12 + 4*612) * 4)
__global__ __launch_bounds__(256, 1) void k_main(const float* __restrict__ x,
                                                 float* __restrict__ out)
{
    extern __shared__ float sm[];
    float* xs   = sm;                    // 64*612
    float* wbuf = sm + CIN*612;          // 3072 (16B aligned: 39168*4 B)
    float* t2s  = wbuf + 4*CIN*12;       // 4*612
    const int tid = threadIdx.x;
    const int tx  = tid & 31;
    const int ty  = tid >> 5;
    const int r0  = ty * 2;
    const int b   = blockIdx.z;
    const int ty0 = blockIdx.y * 16;
    const int tx0 = blockIdx.x * 32;

    const float* xb = x + (size_t)b*CIN*HWSZ;
    for (int i = tid; i < CIN*612; i += 256) {
        int ch = i / 612, rem = i % 612;
        int rr = rem / 34, cc = rem % 34;
        int gy = ty0 + rr - 1, gx = tx0 + cc - 1;
        float v = 0.f;
        if ((unsigned)gy < HH && (unsigned)gx < WW)
            v = xb[(size_t)ch*HWSZ + gy*WW + gx];
        xs[i] = v;
    }
    __syncthreads();

    float* ob = out + (size_t)b*NSEL*HWSZ;
    const int gy = ty0 + r0, gx = tx0 + tx;

    // ---- main branch: 3x3 over x, 4 oc per iteration ----
    const int nm = g_cnt[0];
    for (int k = 0; k < nm; k += 4) {
        for (int i = tid; i < 4*CIN*12; i += 256) {
            int g = i / (CIN*12), rem = i % (CIN*12), ic = rem / 12, j = rem % 12;
            wbuf[i] = (j < 9) ? g_wm[(g_lch[0][k+g]*CIN + ic)*9 + j] : 0.f;
        }
        __syncthreads();
        float acc0[4] = {0,0,0,0}, acc1[4] = {0,0,0,0};
        #pragma unroll 2
        for (int ic = 0; ic < CIN; ic++) {
            const float* p = xs + ic*612 + r0*34 + tx;
            float v00=p[0],  v01=p[1],  v02=p[2];
            float v10=p[34], v11=p[35], v12=p[36];
            float v20=p[68], v21=p[69], v22=p[70];
            float v30=p[102],v31=p[103],v32=p[104];
            #pragma unroll
            for (int g = 0; g < 4; g++) {
                const float4* wp = (const float4*)(wbuf + (g*CIN + ic)*12);
                float4 wa = wp[0], wb = wp[1], wc = wp[2];
                acc0[g] += v00*wa.x + v01*wa.y + v02*wa.z
                         + v10*wa.w + v11*wb.x + v12*wb.y
                         + v20*wb.z + v21*wb.w + v22*wc.x;
                acc1[g] += v10*wa.x + v11*wa.y + v12*wa.z
                         + v20*wa.w + v21*wb.x + v22*wb.y
                         + v30*wb.z + v31*wb.w + v32*wc.x;
            }
        }
        #pragma unroll
        for (int g = 0; g < 4; g++) {
            int oc = g_lch[0][k+g], pos = g_lpos[0][k+g];
            float scl = g_lscale[0][k+g], bias = g_bm[oc];
            float* o = ob + (size_t)pos*HWSZ + gy*WW + gx;
            o[0]  = (acc0[g] + bias) * scl;
            o[WW] = (acc1[g] + bias) * scl;
        }
        __syncthreads();
    }

    // ---- 1x1 branch: 4 oc per iteration, float4 weights over ic ----
    const int n1 = g_cnt[1];
    for (int k = 0; k < n1; k += 4) {
        for (int i = tid; i < 4*CIN; i += 256) {
            int g = i >> 6, ic = i & 63;
            wbuf[i] = g_w1[g_lch[1][k+g]*CIN + ic];
        }
        __syncthreads();
        float a0[4] = {0,0,0,0}, a1[4] = {0,0,0,0};
        const float* p0 = xs + (r0+1)*34 + (tx+1);
        #pragma unroll 2
        for (int ic = 0; ic < CIN; ic += 4) {
            float x0 = p0[(ic+0)*612], x1 = p0[(ic+1)*612],
                  x2 = p0[(ic+2)*612], x3 = p0[(ic+3)*612];
            float y0 = p0[(ic+0)*612+34], y1 = p0[(ic+1)*612+34],
                  y2 = p0[(ic+2)*612+34], y3 = p0[(ic+3)*612+34];
            #pragma unroll
            for (int g = 0; g < 4; g++) {
                float4 w = *(const float4*)(wbuf + g*CIN + ic);
                a0[g] += x0*w.x + x1*w.y + x2*w.z + x3*w.w;
                a1[g] += y0*w.x + y1*w.y + y2*w.z + y3*w.w;
            }
        }
        #pragma unroll
        for (int g = 0; g < 4; g++) {
            int oc = g_lch[1][k+g], pos = g_lpos[1][k+g];
            float scl = g_lscale[1][k+g], bias = g_b1[oc];
            float* o = ob + (size_t)pos*HWSZ + gy*WW + gx;
            o[0]  = (a0[g] + bias) * scl;
            o[WW] = (a1[g] + bias) * scl;
        }
        __syncthreads();
    }

    // ---- avg branch: folded 1x1 at 612 halo positions -> 3x3 sum, 4 oc/iter ----
    const int na = g_cnt[3];
    for (int k = 0; k < na; k += 4) {
        for (int i = tid; i < 4*CIN; i += 256) {
            int g = i >> 6, ic = i & 63;
            wbuf[i] = g_wa[g_lch[3][k+g]*CIN + ic];
        }
        __syncthreads();
        for (int i = tid; i < 612; i += 256) {
            int rr = i / 34, cc = i % 34;
            int yy = ty0 + rr - 1, xx = tx0 + cc - 1;
            float s[4];
            if ((unsigned)yy < HH && (unsigned)xx < WW) {
                #pragma unroll
                for (int g = 0; g < 4; g++) s[g] = g_ba1[g_lch[3][k+g]];
                const float* p = xs + i;
                #pragma unroll 2
                for (int ic = 0; ic < CIN; ic += 4) {
                    float x0 = p[(ic+0)*612], x1 = p[(ic+1)*612],
                          x2 = p[(ic+2)*612], x3 = p[(ic+3)*612];
                    #pragma unroll
                    for (int g = 0; g < 4; g++) {
                        float4 w = *(const float4*)(wbuf + g*CIN + ic);
                        s[g] += x0*w.x + x1*w.y + x2*w.z + x3*w.w;
                    }
                }
            } else {
                s[0] = s[1] = s[2] = s[3] = 0.f;
            }
            #pragma unroll
            for (int g = 0; g < 4; g++) t2s[g*612 + i] = s[g];
        }
        __syncthreads();
        #pragma unroll
        for (int g = 0; g < 4; g++) {
            int oc = g_lch[3][k+g], pos = g_lpos[3][k+g];
            float scl = g_lscale[3][k+g], ba2 = g_ba2[oc];
            const float* q = t2s + g*612 + r0*34 + tx;
            float m0 = q[34]+q[35]+q[36] + q[68]+q[69]+q[70];
            float s0 = q[0]+q[1]+q[2] + m0;
            float s1 = m0 + q[102]+q[103]+q[104];
            float* o = ob + (size_t)pos*HWSZ + gy*WW + gx;
            o[0]  = (s0 + ba2) * scl;
            o[WW] = (s1 + ba2) * scl;
        }
        __syncthreads();
    }
}

// ---------------- 3x3 branch: conv3x3 over t1 (32 ch), 4 oc/iter ----------------
#define SMEM_B ((MID*612 + 4*MID*12) * 4)
__global__ __launch_bounds__(256) void k_b3(float* __restrict__ out)
{
    extern __shared__ float sm[];
    float* t1s  = sm;                 // 32*612
    float* wbuf = sm + MID*612;       // 4*32*12 (offset 19584*4 B, 16B aligned)
    const int tid = threadIdx.x;
    const int tx  = tid & 31;
    const int ty  = tid >> 5;
    const int r0  = ty * 2;
    const int b   = blockIdx.z;
    const int ty0 = blockIdx.y * 16;
    const int tx0 = blockIdx.x * 32;

    const float* tb = g_t1 + (size_t)b*MID*HWSZ;
    for (int i = tid; i < MID*612; i += 256) {
        int ch = i / 612, rem = i % 612;
        int rr = rem / 34, cc = rem % 34;
        int gy = ty0 + rr - 1, gx = tx0 + cc - 1;
        float v = 0.f;
        if ((unsigned)gy < HH && (unsigned)gx < WW)
            v = tb[(size_t)ch*HWSZ + gy*WW + gx];
        t1s[i] = v;
    }
    __syncthreads();

    float* ob = out + (size_t)b*NSEL*HWSZ;
    const int gy = ty0 + r0, gx = tx0 + tx;
    const int n3 = g_cnt[2];
    for (int k = 0; k < n3; k += 4) {
        for (int i = tid; i < 4*MID*12; i += 256) {
            int g = i / (MID*12), rem = i % (MID*12), ic = rem / 12, j = rem % 12;
            wbuf[i] = (j < 9) ? g_wp2[(g_lch[2][k+g]*MID + ic)*9 + j] : 0.f;
        }
        __syncthreads();
        float acc0[4] = {0,0,0,0}, acc1[4] = {0,0,0,0};
        #pragma unroll 2
        for (int ic = 0; ic < MID; ic++) {
            const float* p = t1s + ic*612 + r0*34 + tx;
            float v00=p[0],  v01=p[1],  v02=p[2];
            float v10=p[34], v11=p[35], v12=p[36];
            float v20=p[68], v21=p[69], v22=p[70];
            float v30=p[102],v31=p[103],v32=p[104];
            #pragma unroll
            for (int g = 0; g < 4; g++) {
                const float4* wp = (const float4*)(wbuf + (g*MID + ic)*12);
                float4 wa = wp[0], wb = wp[1], wc = wp[2];
                acc0[g] += v00*wa.x + v01*wa.y + v02*wa.z
                         + v10*wa.w + v11*wb.x + v12*wb.y
                         + v20*wb.z + v21*wb.w + v22*wc.x;
                acc1[g] += v10*wa.x + v11*wa.y + v12*wa.z
                         + v20*wa.w + v21*wb.x + v22*wb.y
                         + v30*wb.z + v31*wb.w + v32*wc.x;
            }
        }
        #pragma unroll
        for (int g = 0; g < 4; g++) {
            int oc = g_lch[2][k+g], pos = g_lpos[2][k+g];
            float scl = g_lscale[2][k+g], bias = g_bp2[oc];
            float* o = ob + (size_t)pos*HWSZ + gy*WW + gx;
            o[0]  = (acc0[g] + bias) * scl;
            o[WW] = (acc1[g] + bias) * scl;
        }
        __syncthreads();
    }
}

// ---------------- launch ----------------
extern "C" void kernel_launch(void* const* d_in, const int* in_sizes, int n_in,
                              void* d_out, int out_size)
{
    const float* x       = (const float*)d_in[0];
    const float* w_main  = (const float*)d_in[1];
    const float* bn_main = (const float*)d_in[2];
    const float* w_1x1   = (const float*)d_in[3];
    const float* bn_1x1  = (const float*)d_in[4];
    const float* w31     = (const float*)d_in[5];
    const float* bn31    = (const float*)d_in[6];
    const float* w32     = (const float*)d_in[7];
    const float* bn32    = (const float*)d_in[8];
    const float* w_avg   = (const float*)d_in[9];
    const float* bnA1    = (const float*)d_in[10];
    const float* bnA2    = (const float*)d_in[11];
    const float* c_score = (const float*)d_in[12];
    float* out = (float*)d_out;

    cudaFuncSetAttribute(k_t1,   cudaFuncAttributeMaxDynamicSharedMemorySize, SMEM_T1);
    cudaFuncSetAttribute(k_main, cudaFuncAttributeMaxDynamicSharedMemorySize, SMEM_A);
    cudaFuncSetAttribute(k_b3,   cudaFuncAttributeMaxDynamicSharedMemorySize, SMEM_B);

    k_setup<<<1, 256>>>(w_main, bn_main, w_1x1, bn_1x1, w31, bn31, w32, bn32,
                        w_avg, bnA1, bnA2, c_score);
    k_t1<<<BATCH*HH/2, 256, SMEM_T1>>>(x);
    dim3 grid(WW/32, HH/16, BATCH);
    k_main<<<grid, 256, SMEM_A>>>(x, out);
    k_b3<<<grid, 256, SMEM_B>>>(out);
}